// round 13
// baseline (speedup 1.0000x reference)
#include <cuda_runtime.h>
#include <cuda_bf16.h>
#include <cuda_fp16.h>

#define NN 20000     // nodes
#define NP 20096     // padded rows (multiple of 128)
#define EE 500000    // edges
#define DD 256       // feature dim
#define SK 1600      // S row stride in HALF units (kt max 1568, padded)
#define WKP 800      // Wcat kp-rows (half2 along k) per stage
#define ECAP 128     // staged edges per node in smem (fallback to global beyond)

// ---------------- scratch (static device memory; no allocs) ----------------
__device__ float    g_xs[4][NN * DD];                 // xs[0..3] fp32 (residual path)
__device__ unsigned g_xh[4][NN * DD / 2];             // xs[0..3] fp16 mirror (gather path)
__device__ unsigned g_S[(size_t)NP * (SK / 2)];       // S rows half2-packed along k
__device__ unsigned g_Wcat[4][WKP * DD];              // per-stage weights+bias, half2 along k
__device__ int      g_deg[NN];
__device__ int      g_rowptr[NN + 1];
__device__ int      g_cursor[NN];
__device__ int      g_cnt[NN * 8];                    // per-node bucket counts (6 used)
__device__ int2     g_edge[EE];                       // (src, etype | hop<<2), grouped by dst

// ---------------- setup ----------------
__global__ void setup_kernel(const float* __restrict__ x) {
    int i = blockIdx.x * blockDim.x + threadIdx.x;
    if (i < NN * DD / 2) {
        float2 v = *(const float2*)(x + 2 * i);
        *(float2*)(g_xs[0] + 2 * i) = v;
        __half2 h = __floats2half2_rn(v.x, v.y);
        g_xh[0][i] = *(unsigned*)&h;
    }
    if (i < NN) g_deg[i] = 0;
    if (i < NN * 8) g_cnt[i] = 0;
}

// Wcat k-rows: [0,768)=W_edge[t]; [768,768+256t)=W_hop[t,j<t]; [biasr,biasr+6)=bias; else 0.
__global__ void pack_w_kernel(const float* __restrict__ We, const float* __restrict__ be,
                              const float* __restrict__ Wh, const float* __restrict__ bh) {
    int idx = blockIdx.x * blockDim.x + threadIdx.x;
    if (idx >= 4 * WKP * DD) return;
    int t = idx / (WKP * DD);
    int rem = idx - t * (WKP * DD);
    int kp = rem / DD;
    int c = rem - kp * DD;
    int biasr = 768 + 256 * t;
    float v[2];
    #pragma unroll
    for (int h = 0; h < 2; h++) {
        int r = 2 * kp + h;
        float val = 0.f;
        if (r < 768) {
            val = We[(size_t)((t * 3 + (r >> 8)) * 256 + (r & 255)) * DD + c];
        } else if (r < biasr) {
            int j = (r - 768) >> 8, k = (r - 768) & 255;
            val = Wh[(size_t)((t * 3 + j) * 256 + k) * DD + c];
        } else if (r < biasr + 6) {
            int b = r - biasr;
            if (b < 3) val = be[(size_t)(t * 3 + b) * DD + c];
            else if (b - 3 < t) val = bh[(size_t)(t * 3 + (b - 3)) * DD + c];
        }
        v[h] = val;
    }
    __half2 p = __floats2half2_rn(v[0], v[1]);
    g_Wcat[t][kp * DD + c] = *(unsigned*)&p;
}

__global__ void deg_kernel(const int* __restrict__ ei) {
    int i = blockIdx.x * blockDim.x + threadIdx.x;
    if (i < EE) atomicAdd(&g_deg[ei[EE + i]], 1);
}

// exclusive scan of g_deg, single block of 1024 threads
__global__ void scan_kernel() {
    __shared__ int wsum[32];
    __shared__ int carry_s;
    int tid = threadIdx.x, lane = tid & 31, w = tid >> 5;
    if (tid == 0) carry_s = 0;
    __syncthreads();
    for (int base = 0; base < NN; base += 1024) {
        int i = base + tid;
        int v = (i < NN) ? g_deg[i] : 0;
        int x = v;
        #pragma unroll
        for (int o = 1; o < 32; o <<= 1) {
            int y = __shfl_up_sync(0xffffffffu, x, o);
            if (lane >= o) x += y;
        }
        if (lane == 31) wsum[w] = x;
        __syncthreads();
        if (w == 0) {
            int s = wsum[lane];
            #pragma unroll
            for (int o = 1; o < 32; o <<= 1) {
                int y = __shfl_up_sync(0xffffffffu, s, o);
                if (lane >= o) s += y;
            }
            wsum[lane] = s;
        }
        __syncthreads();
        int excl = carry_s + (w ? wsum[w - 1] : 0) + (x - v);
        if (i < NN) { g_rowptr[i] = excl; g_cursor[i] = excl; }
        int total = wsum[31];
        __syncthreads();
        if (tid == 0) carry_s += total;
        __syncthreads();
    }
    if (tid == 0) g_rowptr[NN] = carry_s;
}

__global__ void fill_kernel(const int* __restrict__ ei, const int* __restrict__ attr) {
    int i = blockIdx.x * blockDim.x + threadIdx.x;
    if (i >= EE) return;
    int src = ei[i];
    int dst = ei[EE + i];
    int hop = attr[2 * i + 0];
    int et  = attr[2 * i + 1];
    int pos = atomicAdd(&g_cursor[dst], 1);
    g_edge[pos] = make_int2(src, et | (hop << 2));
    atomicAdd(&g_cnt[dst * 8 + et], 1);
    if (hop >= 2) atomicAdd(&g_cnt[dst * 8 + 3 + (hop - 2)], 1);
}

// ---------------- aggregation ----------------
// 4 nodes/block, 64 threads/node. Edge records STAGED IN SMEM (kills the
// L2->L2 dependent-load chain; per-iter chain becomes LDS(29) -> gather(234)).
// 4-edge unroll with front-batched fp16 gathers (MLP ~8), fp32 accumulate.
__device__ __forceinline__ void st4h(__half* p, float4 v) {
    __half2 lo = __floats2half2_rn(v.x, v.y);
    __half2 hi = __floats2half2_rn(v.z, v.w);
    uint2 u;
    u.x = *(unsigned*)&lo;
    u.y = *(unsigned*)&hi;
    *(uint2*)p = u;
}
__device__ __forceinline__ void acch(float4& a, uint2 u) {
    __half2 p0 = *(__half2*)&u.x;
    __half2 p1 = *(__half2*)&u.y;
    float2 f0 = __half22float2(p0);
    float2 f1 = __half22float2(p1);
    a.x += f0.x; a.y += f0.y; a.z += f1.x; a.w += f1.y;
}

__global__ __launch_bounds__(256) void agg_kernel(int t) {
    __shared__ int2 se[4][ECAP];
    int sub  = threadIdx.x >> 6;
    int lane = threadIdx.x & 63;
    int n = blockIdx.x * 4 + sub;
    bool valid = (n < NN);
    int beg = 0, end = 0;
    if (valid) { beg = g_rowptr[n]; end = g_rowptr[n + 1]; }
    int deg = end - beg;
    int dstage = deg < ECAP ? deg : ECAP;
    // stage this node's edge records into smem
    for (int i = lane; i < dstage; i += 64)
        se[sub][i] = g_edge[beg + i];
    __syncthreads();
    if (!valid) return;

    int cp0 = lane << 1;                          // half2-pair index (covers 4 cols)
    const unsigned* xht = g_xh[t];
    const unsigned* xhb = g_xh[0];                // delayed array j = xhb + (t-1-j)*(NN*DD/2)
    unsigned tu = (unsigned)t;
    const uint2 uz = make_uint2(0u, 0u);

    float4 z = {0.f, 0.f, 0.f, 0.f};
    float4 a0 = z, a1 = z, a2 = z, h0 = z, h1 = z, h2 = z;

    int i = 0;
    for (; i + 4 <= dstage; i += 4) {
        int2 e0 = se[sub][i],     e1 = se[sub][i + 1];
        int2 e2 = se[sub][i + 2], e3 = se[sub][i + 3];
        uint2 v0 = *(const uint2*)(xht + (size_t)e0.x * (DD / 2) + cp0);
        uint2 v1 = *(const uint2*)(xht + (size_t)e1.x * (DD / 2) + cp0);
        uint2 v2 = *(const uint2*)(xht + (size_t)e2.x * (DD / 2) + cp0);
        uint2 v3 = *(const uint2*)(xht + (size_t)e3.x * (DD / 2) + cp0);
        int j0 = (e0.y >> 2) - 2, j1 = (e1.y >> 2) - 2;
        int j2 = (e2.y >> 2) - 2, j3 = (e3.y >> 2) - 2;
        bool hb0 = (unsigned)j0 < tu, hb1 = (unsigned)j1 < tu;
        bool hb2 = (unsigned)j2 < tu, hb3 = (unsigned)j3 < tu;
        uint2 w0 = uz, w1 = uz, w2 = uz, w3 = uz;
        if (hb0) w0 = *(const uint2*)(xhb + (size_t)(t - 1 - j0) * (NN * DD / 2) + (size_t)e0.x * (DD / 2) + cp0);
        if (hb1) w1 = *(const uint2*)(xhb + (size_t)(t - 1 - j1) * (NN * DD / 2) + (size_t)e1.x * (DD / 2) + cp0);
        if (hb2) w2 = *(const uint2*)(xhb + (size_t)(t - 1 - j2) * (NN * DD / 2) + (size_t)e2.x * (DD / 2) + cp0);
        if (hb3) w3 = *(const uint2*)(xhb + (size_t)(t - 1 - j3) * (NN * DD / 2) + (size_t)e3.x * (DD / 2) + cp0);
        int et0 = e0.y & 3, et1 = e1.y & 3, et2 = e2.y & 3, et3 = e3.y & 3;
        if (et0 == 0) acch(a0, v0); else if (et0 == 1) acch(a1, v0); else acch(a2, v0);
        if (et1 == 0) acch(a0, v1); else if (et1 == 1) acch(a1, v1); else acch(a2, v1);
        if (et2 == 0) acch(a0, v2); else if (et2 == 1) acch(a1, v2); else acch(a2, v2);
        if (et3 == 0) acch(a0, v3); else if (et3 == 1) acch(a1, v3); else acch(a2, v3);
        if (hb0) { if (j0 == 0) acch(h0, w0); else if (j0 == 1) acch(h1, w0); else acch(h2, w0); }
        if (hb1) { if (j1 == 0) acch(h0, w1); else if (j1 == 1) acch(h1, w1); else acch(h2, w1); }
        if (hb2) { if (j2 == 0) acch(h0, w2); else if (j2 == 1) acch(h1, w2); else acch(h2, w2); }
        if (hb3) { if (j3 == 0) acch(h0, w3); else if (j3 == 1) acch(h1, w3); else acch(h2, w3); }
    }
    for (; i < dstage; ++i) {
        int2 e0 = se[sub][i];
        uint2 v0 = *(const uint2*)(xht + (size_t)e0.x * (DD / 2) + cp0);
        int j0 = (e0.y >> 2) - 2;
        bool hb0 = (unsigned)j0 < tu;
        uint2 w0 = uz;
        if (hb0) w0 = *(const uint2*)(xhb + (size_t)(t - 1 - j0) * (NN * DD / 2) + (size_t)e0.x * (DD / 2) + cp0);
        int et0 = e0.y & 3;
        if (et0 == 0) acch(a0, v0); else if (et0 == 1) acch(a1, v0); else acch(a2, v0);
        if (hb0) { if (j0 == 0) acch(h0, w0); else if (j0 == 1) acch(h1, w0); else acch(h2, w0); }
    }
    // overflow fallback (degree > ECAP): read edge records from global
    for (int gi = beg + dstage; gi < end; ++gi) {
        int2 e0 = g_edge[gi];
        uint2 v0 = *(const uint2*)(xht + (size_t)e0.x * (DD / 2) + cp0);
        int j0 = (e0.y >> 2) - 2;
        bool hb0 = (unsigned)j0 < tu;
        uint2 w0 = uz;
        if (hb0) w0 = *(const uint2*)(xhb + (size_t)(t - 1 - j0) * (NN * DD / 2) + (size_t)e0.x * (DD / 2) + cp0);
        int et0 = e0.y & 3;
        if (et0 == 0) acch(a0, v0); else if (et0 == 1) acch(a1, v0); else acch(a2, v0);
        if (hb0) { if (j0 == 0) acch(h0, w0); else if (j0 == 1) acch(h1, w0); else acch(h2, w0); }
    }

    int c0 = cp0 << 1;
    __half* srow = (__half*)g_S + (size_t)n * SK;
    st4h(srow + 0 * 256 + c0, a0);
    st4h(srow + 1 * 256 + c0, a1);
    st4h(srow + 2 * 256 + c0, a2);
    if (t >= 1) st4h(srow + 768 + c0, h0);
    if (t >= 2) st4h(srow + 1024 + c0, h1);
    if (t >= 3) st4h(srow + 1280 + c0, h2);
    // counts at k = [768+256t, +6), zeros to +32 (pads kt to a multiple of 32)
    if (lane < 8) {
        int cc = lane * 4;
        float4 u = z;
        if (cc + 0 < 6) u.x = (float)g_cnt[n * 8 + cc + 0];
        if (cc + 1 < 6) u.y = (float)g_cnt[n * 8 + cc + 1];
        if (cc + 2 < 6) u.z = (float)g_cnt[n * 8 + cc + 2];
        if (cc + 3 < 6) u.w = (float)g_cnt[n * 8 + cc + 3];
        st4h(srow + 768 + 256 * t + cc, u);
    }
}

// ---------------- fp16 tensor-core GEMM, 3-stage cp.async pipeline ----------------
// out = x_t + relu(S @ Wcat)  (bias rides in K); epilogue also writes fp16 mirror of xout.
#define TBM 128
#define TBN 128
#define TBK 32
#define AS_LD 20     // kp stride (uint/half2 units) for As[128][20]
#define BS_LD 136    // col stride (uint/half2 units) for Bs[16][136]
#define NSTG 3

__device__ __forceinline__ void cp16(void* dst_smem, const void* src) {
    unsigned d = (unsigned)__cvta_generic_to_shared(dst_smem);
    asm volatile("cp.async.ca.shared.global [%0], [%1], 16;" :: "r"(d), "l"(src));
}
#define CP_COMMIT()  asm volatile("cp.async.commit_group;")
#define CP_WAIT(n)   asm volatile("cp.async.wait_group %0;" :: "n"(n))

__global__ __launch_bounds__(256) void gemm_tc_kernel(int t, int kt,
                                                      float* __restrict__ dfinal) {
    __shared__ __align__(16) unsigned As[NSTG][TBM * AS_LD];       // [row][kp] half2
    __shared__ __align__(16) unsigned Bs[NSTG][(TBK / 2) * BS_LD]; // [kp][col] half2

    const unsigned* Wc = g_Wcat[t];
    const float* xin = g_xs[t];
    float* xout = (t < 3) ? g_xs[t + 1] : dfinal;
    unsigned* xhout = (t < 3) ? g_xh[t + 1] : 0;

    int mblk = blockIdx.x * TBM;
    int nblk = blockIdx.y * TBN;
    int tid  = threadIdx.x;
    int wid  = tid >> 5;
    int lane = tid & 31;
    int wm   = wid & 3;
    int wn   = wid >> 2;
    int g    = lane >> 2;
    int tq   = lane & 3;

    float c[2][8][4];
    #pragma unroll
    for (int mt = 0; mt < 2; mt++)
        #pragma unroll
        for (int nt = 0; nt < 8; nt++)
            #pragma unroll
            for (int i = 0; i < 4; i++) c[mt][nt][i] = 0.f;

    int niter = kt / TBK;

    auto issue = [&](int buf, int kk) {
        int kk2 = kk >> 1;
        const __half* Sh = (const __half*)g_S;
        #pragma unroll
        for (int l = 0; l < 2; ++l) {
            int ca = tid + l * 256;
            int arow = ca >> 2, aseg = ca & 3;
            cp16(&As[buf][arow * AS_LD + aseg * 4],
                 Sh + (size_t)(mblk + arow) * SK + kk + aseg * 8);
            int brow = ca >> 5, bseg = ca & 31;
            cp16(&Bs[buf][brow * BS_LD + bseg * 4],
                 Wc + (size_t)(kk2 + brow) * DD + nblk + bseg * 4);
        }
    };

    issue(0, 0); CP_COMMIT();
    if (niter > 1) { issue(1, TBK); CP_COMMIT(); }

    for (int i = 0; i < niter; ++i) {
        int cur = i % NSTG;
        if (i + 2 < niter) {
            issue((i + 2) % NSTG, (i + 2) * TBK);
            CP_COMMIT();
            CP_WAIT(2);
        } else if (i + 1 < niter) {
            CP_WAIT(1);
        } else {
            CP_WAIT(0);
        }
        __syncthreads();

        #pragma unroll
        for (int kc = 0; kc < 2; ++kc) {
            int kp0 = kc * 8;
            unsigned a[2][4];
            #pragma unroll
            for (int mt = 0; mt < 2; mt++) {
                int r = wm * 32 + mt * 16 + g;
                a[mt][0] = As[cur][r * AS_LD + kp0 + tq];
                a[mt][1] = As[cur][(r + 8) * AS_LD + kp0 + tq];
                a[mt][2] = As[cur][r * AS_LD + kp0 + tq + 4];
                a[mt][3] = As[cur][(r + 8) * AS_LD + kp0 + tq + 4];
            }
            #pragma unroll
            for (int nt = 0; nt < 8; nt++) {
                int nb = wn * 64 + nt * 8;
                unsigned b0 = Bs[cur][(kp0 + tq) * BS_LD + nb + g];
                unsigned b1 = Bs[cur][(kp0 + tq + 4) * BS_LD + nb + g];
                #pragma unroll
                for (int mt = 0; mt < 2; mt++) {
                    asm volatile(
                        "mma.sync.aligned.m16n8k16.row.col.f32.f16.f16.f32 "
                        "{%0,%1,%2,%3}, {%4,%5,%6,%7}, {%8,%9}, {%0,%1,%2,%3};\n"
                        : "+f"(c[mt][nt][0]), "+f"(c[mt][nt][1]),
                          "+f"(c[mt][nt][2]), "+f"(c[mt][nt][3])
                        : "r"(a[mt][0]), "r"(a[mt][1]), "r"(a[mt][2]), "r"(a[mt][3]),
                          "r"(b0), "r"(b1));
                }
            }
        }
        __syncthreads();
    }

    // epilogue: residual + relu; also write fp16 mirror for next stage's gathers
    #pragma unroll
    for (int nt = 0; nt < 8; nt++) {
        int col = nblk + wn * 64 + nt * 8 + 2 * tq;
        #pragma unroll
        for (int mt = 0; mt < 2; mt++) {
            #pragma unroll
            for (int half = 0; half < 2; half++) {
                int r = mblk + wm * 32 + mt * 16 + g + half * 8;
                if (r >= NN) continue;
                float2 xr = *(const float2*)(xin + (size_t)r * DD + col);
                float2 o;
                o.x = xr.x + fmaxf(c[mt][nt][half * 2 + 0], 0.f);
                o.y = xr.y + fmaxf(c[mt][nt][half * 2 + 1], 0.f);
                *(float2*)(xout + (size_t)r * DD + col) = o;
                if (xhout) {
                    __half2 hh = __floats2half2_rn(o.x, o.y);
                    xhout[((size_t)r * DD + col) >> 1] = *(unsigned*)&hh;
                }
            }
        }
    }
}

// ---------------- driver ----------------
extern "C" void kernel_launch(void* const* d_in, const int* in_sizes, int n_in,
                              void* d_out, int out_size) {
    const float* x      = (const float*)d_in[0];
    const int*   ei     = (const int*)d_in[1];
    const int*   attr   = (const int*)d_in[2];
    const float* W_edge = (const float*)d_in[3];
    const float* b_edge = (const float*)d_in[4];
    const float* W_hop  = (const float*)d_in[5];
    const float* b_hop  = (const float*)d_in[6];
    float* out = (float*)d_out;

    setup_kernel<<<(NN * DD / 2 + 255) / 256, 256>>>(x);
    pack_w_kernel<<<(4 * WKP * DD + 255) / 256, 256>>>(W_edge, b_edge, W_hop, b_hop);
    deg_kernel<<<(EE + 255) / 256, 256>>>(ei);
    scan_kernel<<<1, 1024>>>();
    fill_kernel<<<(EE + 255) / 256, 256>>>(ei, attr);

    dim3 ggrid(NP / TBM, DD / TBN);              // 157 x 2
    for (int t = 0; t < 4; ++t) {
        agg_kernel<<<(NN + 3) / 4, 256>>>(t);
        int kt = 768 + 256 * t + 32;             // bias/cnt K-block padded to 32
        gemm_tc_kernel<<<ggrid, 256>>>(t, kt, out);
    }
}

// round 15
// speedup vs baseline: 1.1509x; 1.1509x over previous
#include <cuda_runtime.h>
#include <cuda_bf16.h>
#include <cuda_fp16.h>

#define NN 20000     // nodes
#define NP 20096     // padded rows (multiple of 128)
#define EE 500000    // edges
#define DD 256       // feature dim
#define SK 1600      // S row stride in HALF units (kt max 1568, padded)
#define WKP 800      // Wcat kp-rows (half2 along k) per stage

// ---------------- scratch (static device memory; no allocs) ----------------
// NOTE: zero-initialized at module load. g_deg is re-zeroed by scan_kernel
// (read-then-clear) and g_cnt by agg_kernel<3> (read-then-clear), making the
// whole launch sequence self-restoring across CUDA-graph replays.
__device__ float    g_xs[4][NN * DD];                 // xs[0..3] fp32 (residual path)
__device__ unsigned g_xh[4][NN * DD / 2];             // xs[0..3] fp16 mirror (gather path)
__device__ unsigned g_S[(size_t)NP * (SK / 2)];       // S rows half2-packed along k
__device__ unsigned g_Wcat[4][WKP * DD];              // per-stage weights+bias, half2 along k
__device__ int      g_deg[NN];
__device__ int      g_rowptr[NN + 1];
__device__ int      g_cursor[NN];
__device__ int      g_cnt[NN * 8];                    // per-node bucket counts (6 used)
__device__ int2     g_edge[EE];                       // (src, etype | hop<<2), grouped by dst

// ---------------- launch 1: copy x (fp32 + fp16 mirror) + degree histogram ----------------
// g_deg is zero on entry (initial static zero, then re-zeroed by scan each replay).
__global__ void copydeg_kernel(const float* __restrict__ x, const int* __restrict__ ei) {
    int i = blockIdx.x * blockDim.x + threadIdx.x;
    if (i < NN * DD / 2) {
        float2 v = *(const float2*)(x + 2 * i);
        *(float2*)(g_xs[0] + 2 * i) = v;
        __half2 h = __floats2half2_rn(v.x, v.y);
        g_xh[0][i] = *(unsigned*)&h;
    }
    if (i < EE) atomicAdd(&g_deg[ei[EE + i]], 1);
}

// ---------------- launch 2: exclusive scan of g_deg (single block, 1024 thr) ----------------
// Also clears g_deg for the next graph replay.
__global__ void scan_kernel() {
    __shared__ int wsum[32];
    __shared__ int carry_s;
    int tid = threadIdx.x, lane = tid & 31, w = tid >> 5;
    if (tid == 0) carry_s = 0;
    __syncthreads();
    for (int base = 0; base < NN; base += 1024) {
        int i = base + tid;
        int v = 0;
        if (i < NN) { v = g_deg[i]; g_deg[i] = 0; }   // read-then-clear (replay-safe)
        int x = v;
        #pragma unroll
        for (int o = 1; o < 32; o <<= 1) {
            int y = __shfl_up_sync(0xffffffffu, x, o);
            if (lane >= o) x += y;
        }
        if (lane == 31) wsum[w] = x;
        __syncthreads();
        if (w == 0) {
            int s = wsum[lane];
            #pragma unroll
            for (int o = 1; o < 32; o <<= 1) {
                int y = __shfl_up_sync(0xffffffffu, s, o);
                if (lane >= o) s += y;
            }
            wsum[lane] = s;
        }
        __syncthreads();
        int excl = carry_s + (w ? wsum[w - 1] : 0) + (x - v);
        if (i < NN) { g_rowptr[i] = excl; g_cursor[i] = excl; }
        int total = wsum[31];
        __syncthreads();
        if (tid == 0) carry_s += total;
        __syncthreads();
    }
    if (tid == 0) g_rowptr[NN] = carry_s;
}

// ---------------- launch 3: scatter edges into dst-grouped list + bucket counts ----------------
// g_cnt is zero on entry (initial static zero, then re-zeroed by agg<3> each replay).
__global__ void fill_kernel(const int* __restrict__ ei, const int* __restrict__ attr) {
    int i = blockIdx.x * blockDim.x + threadIdx.x;
    if (i >= EE) return;
    int src = ei[i];
    int dst = ei[EE + i];
    int hop = attr[2 * i + 0];
    int et  = attr[2 * i + 1];
    int pos = atomicAdd(&g_cursor[dst], 1);
    g_edge[pos] = make_int2(src, et | (hop << 2));
    atomicAdd(&g_cnt[dst * 8 + et], 1);
    if (hop >= 2) atomicAdd(&g_cnt[dst * 8 + 3 + (hop - 2)], 1);
}

// ---------------- pack Wcat (independent; launched after agg<0>) ----------------
// Wcat k-rows: [0,768)=W_edge[t]; [768,768+256t)=W_hop[t,j<t]; [biasr,biasr+6)=bias; else 0.
__global__ void pack_w_kernel(const float* __restrict__ We, const float* __restrict__ be,
                              const float* __restrict__ Wh, const float* __restrict__ bh) {
    int idx = blockIdx.x * blockDim.x + threadIdx.x;
    if (idx >= 4 * WKP * DD) return;
    int t = idx / (WKP * DD);
    int rem = idx - t * (WKP * DD);
    int kp = rem / DD;
    int c = rem - kp * DD;
    int biasr = 768 + 256 * t;
    float v[2];
    #pragma unroll
    for (int h = 0; h < 2; h++) {
        int r = 2 * kp + h;
        float val = 0.f;
        if (r < 768) {
            val = We[(size_t)((t * 3 + (r >> 8)) * 256 + (r & 255)) * DD + c];
        } else if (r < biasr) {
            int j = (r - 768) >> 8, k = (r - 768) & 255;
            val = Wh[(size_t)((t * 3 + j) * 256 + k) * DD + c];
        } else if (r < biasr + 6) {
            int b = r - biasr;
            if (b < 3) val = be[(size_t)(t * 3 + b) * DD + c];
            else if (b - 3 < t) val = bh[(size_t)(t * 3 + (b - 3)) * DD + c];
        }
        v[h] = val;
    }
    __half2 p = __floats2half2_rn(v[0], v[1]);
    g_Wcat[t][kp * DD + c] = *(unsigned*)&p;
}

// ---------------- aggregation (R11-proven loop, templated on stage T) ----------------
// 4 nodes/block, 64 threads/node, fp16 gathers (8B/edge/thread), 4-edge unroll
// with front-batched loads. At T=0 the whole hop path is compiled out.
__device__ __forceinline__ void st4h(__half* p, float4 v) {
    __half2 lo = __floats2half2_rn(v.x, v.y);
    __half2 hi = __floats2half2_rn(v.z, v.w);
    uint2 u;
    u.x = *(unsigned*)&lo;
    u.y = *(unsigned*)&hi;
    *(uint2*)p = u;
}
__device__ __forceinline__ void acch(float4& a, uint2 u) {
    __half2 p0 = *(__half2*)&u.x;
    __half2 p1 = *(__half2*)&u.y;
    float2 f0 = __half22float2(p0);
    float2 f1 = __half22float2(p1);
    a.x += f0.x; a.y += f0.y; a.z += f1.x; a.w += f1.y;
}

template<int T>
__global__ __launch_bounds__(256) void agg_kernel() {
    int sub = threadIdx.x >> 6;
    int n = blockIdx.x * 4 + sub;
    if (n >= NN) return;
    int lane = threadIdx.x & 63;
    int cp0 = lane << 1;                          // half2-pair index (covers 4 cols)
    int beg = g_rowptr[n], end = g_rowptr[n + 1];
    const unsigned* xht = g_xh[T];
    const unsigned* xhb = g_xh[0];                // delayed array j = xhb + (T-1-j)*(NN*DD/2)
    const uint2 uz = make_uint2(0u, 0u);

    float4 z = {0.f, 0.f, 0.f, 0.f};
    float4 a0 = z, a1 = z, a2 = z, h0 = z, h1 = z, h2 = z;

    int i = beg;
    for (; i + 4 <= end; i += 4) {
        int2 e0 = g_edge[i],     e1 = g_edge[i + 1];
        int2 e2 = g_edge[i + 2], e3 = g_edge[i + 3];
        uint2 v0 = *(const uint2*)(xht + (size_t)e0.x * (DD / 2) + cp0);
        uint2 v1 = *(const uint2*)(xht + (size_t)e1.x * (DD / 2) + cp0);
        uint2 v2 = *(const uint2*)(xht + (size_t)e2.x * (DD / 2) + cp0);
        uint2 v3 = *(const uint2*)(xht + (size_t)e3.x * (DD / 2) + cp0);
        int et0 = e0.y & 3, et1 = e1.y & 3, et2 = e2.y & 3, et3 = e3.y & 3;
        if (T > 0) {
            int j0 = (e0.y >> 2) - 2, j1 = (e1.y >> 2) - 2;
            int j2 = (e2.y >> 2) - 2, j3 = (e3.y >> 2) - 2;
            bool hb0 = (unsigned)j0 < (unsigned)T, hb1 = (unsigned)j1 < (unsigned)T;
            bool hb2 = (unsigned)j2 < (unsigned)T, hb3 = (unsigned)j3 < (unsigned)T;
            uint2 w0 = uz, w1 = uz, w2 = uz, w3 = uz;
            if (hb0) w0 = *(const uint2*)(xhb + (size_t)(T - 1 - j0) * (NN * DD / 2) + (size_t)e0.x * (DD / 2) + cp0);
            if (hb1) w1 = *(const uint2*)(xhb + (size_t)(T - 1 - j1) * (NN * DD / 2) + (size_t)e1.x * (DD / 2) + cp0);
            if (hb2) w2 = *(const uint2*)(xhb + (size_t)(T - 1 - j2) * (NN * DD / 2) + (size_t)e2.x * (DD / 2) + cp0);
            if (hb3) w3 = *(const uint2*)(xhb + (size_t)(T - 1 - j3) * (NN * DD / 2) + (size_t)e3.x * (DD / 2) + cp0);
            if (hb0) { if (j0 == 0) acch(h0, w0); else if (j0 == 1) acch(h1, w0); else acch(h2, w0); }
            if (hb1) { if (j1 == 0) acch(h0, w1); else if (j1 == 1) acch(h1, w1); else acch(h2, w1); }
            if (hb2) { if (j2 == 0) acch(h0, w2); else if (j2 == 1) acch(h1, w2); else acch(h2, w2); }
            if (hb3) { if (j3 == 0) acch(h0, w3); else if (j3 == 1) acch(h1, w3); else acch(h2, w3); }
        }
        if (et0 == 0) acch(a0, v0); else if (et0 == 1) acch(a1, v0); else acch(a2, v0);
        if (et1 == 0) acch(a0, v1); else if (et1 == 1) acch(a1, v1); else acch(a2, v1);
        if (et2 == 0) acch(a0, v2); else if (et2 == 1) acch(a1, v2); else acch(a2, v2);
        if (et3 == 0) acch(a0, v3); else if (et3 == 1) acch(a1, v3); else acch(a2, v3);
    }
    for (; i < end; ++i) {
        int2 e0 = g_edge[i];
        uint2 v0 = *(const uint2*)(xht + (size_t)e0.x * (DD / 2) + cp0);
        int et0 = e0.y & 3;
        if (T > 0) {
            int j0 = (e0.y >> 2) - 2;
            bool hb0 = (unsigned)j0 < (unsigned)T;
            uint2 w0 = uz;
            if (hb0) w0 = *(const uint2*)(xhb + (size_t)(T - 1 - j0) * (NN * DD / 2) + (size_t)e0.x * (DD / 2) + cp0);
            if (hb0) { if (j0 == 0) acch(h0, w0); else if (j0 == 1) acch(h1, w0); else acch(h2, w0); }
        }
        if (et0 == 0) acch(a0, v0); else if (et0 == 1) acch(a1, v0); else acch(a2, v0);
    }

    int c0 = cp0 << 1;
    __half* srow = (__half*)g_S + (size_t)n * SK;
    st4h(srow + 0 * 256 + c0, a0);
    st4h(srow + 1 * 256 + c0, a1);
    st4h(srow + 2 * 256 + c0, a2);
    if (T >= 1) st4h(srow + 768 + c0, h0);
    if (T >= 2) st4h(srow + 1024 + c0, h1);
    if (T >= 3) st4h(srow + 1280 + c0, h2);
    // counts at k = [768+256T, +6), zeros to +32 (pads kt to a multiple of 32)
    if (lane < 8) {
        int cc = lane * 4;
        float4 u = z;
        if (cc + 0 < 6) u.x = (float)g_cnt[n * 8 + cc + 0];
        if (cc + 1 < 6) u.y = (float)g_cnt[n * 8 + cc + 1];
        if (cc + 2 < 6) u.z = (float)g_cnt[n * 8 + cc + 2];
        if (cc + 3 < 6) u.w = (float)g_cnt[n * 8 + cc + 3];
        st4h(srow + 768 + 256 * T + cc, u);
        if (T == 3 && lane < 2) {                 // read-then-clear for next replay
            *(int4*)(g_cnt + n * 8 + lane * 4) = make_int4(0, 0, 0, 0);
        }
    }
}

// ---------------- fp16 tensor-core GEMM, 3-stage cp.async pipeline ----------------
// out = x_t + relu(S @ Wcat)  (bias rides in K); epilogue also writes fp16 mirror of xout.
#define TBM 128
#define TBN 128
#define TBK 32
#define AS_LD 20     // kp stride (uint/half2 units) for As[128][20]
#define BS_LD 136    // col stride (uint/half2 units) for Bs[16][136]
#define NSTG 3

__device__ __forceinline__ void cp16(void* dst_smem, const void* src) {
    unsigned d = (unsigned)__cvta_generic_to_shared(dst_smem);
    asm volatile("cp.async.ca.shared.global [%0], [%1], 16;" :: "r"(d), "l"(src));
}
#define CP_COMMIT()  asm volatile("cp.async.commit_group;")
#define CP_WAIT(n)   asm volatile("cp.async.wait_group %0;" :: "n"(n))

__global__ __launch_bounds__(256) void gemm_tc_kernel(int t, int kt,
                                                      float* __restrict__ dfinal) {
    __shared__ __align__(16) unsigned As[NSTG][TBM * AS_LD];       // [row][kp] half2
    __shared__ __align__(16) unsigned Bs[NSTG][(TBK / 2) * BS_LD]; // [kp][col] half2

    const unsigned* Wc = g_Wcat[t];
    const float* xin = g_xs[t];
    float* xout = (t < 3) ? g_xs[t + 1] : dfinal;
    unsigned* xhout = (t < 3) ? g_xh[t + 1] : 0;

    int mblk = blockIdx.x * TBM;
    int nblk = blockIdx.y * TBN;
    int tid  = threadIdx.x;
    int wid  = tid >> 5;
    int lane = tid & 31;
    int wm   = wid & 3;
    int wn   = wid >> 2;
    int g    = lane >> 2;
    int tq   = lane & 3;

    float c[2][8][4];
    #pragma unroll
    for (int mt = 0; mt < 2; mt++)
        #pragma unroll
        for (int nt = 0; nt < 8; nt++)
            #pragma unroll
            for (int i = 0; i < 4; i++) c[mt][nt][i] = 0.f;

    int niter = kt / TBK;

    auto issue = [&](int buf, int kk) {
        int kk2 = kk >> 1;
        const __half* Sh = (const __half*)g_S;
        #pragma unroll
        for (int l = 0; l < 2; ++l) {
            int ca = tid + l * 256;
            int arow = ca >> 2, aseg = ca & 3;
            cp16(&As[buf][arow * AS_LD + aseg * 4],
                 Sh + (size_t)(mblk + arow) * SK + kk + aseg * 8);
            int brow = ca >> 5, bseg = ca & 31;
            cp16(&Bs[buf][brow * BS_LD + bseg * 4],
                 Wc + (size_t)(kk2 + brow) * DD + nblk + bseg * 4);
        }
    };

    issue(0, 0); CP_COMMIT();
    if (niter > 1) { issue(1, TBK); CP_COMMIT(); }

    for (int i = 0; i < niter; ++i) {
        int cur = i % NSTG;
        if (i + 2 < niter) {
            issue((i + 2) % NSTG, (i + 2) * TBK);
            CP_COMMIT();
            CP_WAIT(2);
        } else if (i + 1 < niter) {
            CP_WAIT(1);
        } else {
            CP_WAIT(0);
        }
        __syncthreads();

        #pragma unroll
        for (int kc = 0; kc < 2; ++kc) {
            int kp0 = kc * 8;
            unsigned a[2][4];
            #pragma unroll
            for (int mt = 0; mt < 2; mt++) {
                int r = wm * 32 + mt * 16 + g;
                a[mt][0] = As[cur][r * AS_LD + kp0 + tq];
                a[mt][1] = As[cur][(r + 8) * AS_LD + kp0 + tq];
                a[mt][2] = As[cur][r * AS_LD + kp0 + tq + 4];
                a[mt][3] = As[cur][(r + 8) * AS_LD + kp0 + tq + 4];
            }
            #pragma unroll
            for (int nt = 0; nt < 8; nt++) {
                int nb = wn * 64 + nt * 8;
                unsigned b0 = Bs[cur][(kp0 + tq) * BS_LD + nb + g];
                unsigned b1 = Bs[cur][(kp0 + tq + 4) * BS_LD + nb + g];
                #pragma unroll
                for (int mt = 0; mt < 2; mt++) {
                    asm volatile(
                        "mma.sync.aligned.m16n8k16.row.col.f32.f16.f16.f32 "
                        "{%0,%1,%2,%3}, {%4,%5,%6,%7}, {%8,%9}, {%0,%1,%2,%3};\n"
                        : "+f"(c[mt][nt][0]), "+f"(c[mt][nt][1]),
                          "+f"(c[mt][nt][2]), "+f"(c[mt][nt][3])
                        : "r"(a[mt][0]), "r"(a[mt][1]), "r"(a[mt][2]), "r"(a[mt][3]),
                          "r"(b0), "r"(b1));
                }
            }
        }
        __syncthreads();
    }

    // epilogue: residual + relu; also write fp16 mirror for next stage's gathers
    #pragma unroll
    for (int nt = 0; nt < 8; nt++) {
        int col = nblk + wn * 64 + nt * 8 + 2 * tq;
        #pragma unroll
        for (int mt = 0; mt < 2; mt++) {
            #pragma unroll
            for (int half = 0; half < 2; half++) {
                int r = mblk + wm * 32 + mt * 16 + g + half * 8;
                if (r >= NN) continue;
                float2 xr = *(const float2*)(xin + (size_t)r * DD + col);
                float2 o;
                o.x = xr.x + fmaxf(c[mt][nt][half * 2 + 0], 0.f);
                o.y = xr.y + fmaxf(c[mt][nt][half * 2 + 1], 0.f);
                *(float2*)(xout + (size_t)r * DD + col) = o;
                if (xhout) {
                    __half2 hh = __floats2half2_rn(o.x, o.y);
                    xhout[((size_t)r * DD + col) >> 1] = *(unsigned*)&hh;
                }
            }
        }
    }
}

// ---------------- driver ----------------
extern "C" void kernel_launch(void* const* d_in, const int* in_sizes, int n_in,
                              void* d_out, int out_size) {
    const float* x      = (const float*)d_in[0];
    const int*   ei     = (const int*)d_in[1];
    const int*   attr   = (const int*)d_in[2];
    const float* W_edge = (const float*)d_in[3];
    const float* b_edge = (const float*)d_in[4];
    const float* W_hop  = (const float*)d_in[5];
    const float* b_hop  = (const float*)d_in[6];
    float* out = (float*)d_out;

    int ncopy = NN * DD / 2;                       // 2.56M >= EE, covers both jobs
    copydeg_kernel<<<(ncopy + 255) / 256, 256>>>(x, ei);           // launch 1
    scan_kernel<<<1, 1024>>>();                                     // launch 2
    fill_kernel<<<(EE + 255) / 256, 256>>>(ei, attr);               // launch 3
    agg_kernel<0><<<(NN + 3) / 4, 256>>>();                         // launch 4  (ncu window target)
    pack_w_kernel<<<(4 * WKP * DD + 255) / 256, 256>>>(W_edge, b_edge, W_hop, b_hop); // launch 5
    dim3 ggrid(NP / TBM, DD / TBN);                                 // 157 x 2
    gemm_tc_kernel<<<ggrid, 256>>>(0, 768 + 32, out);               // launch 6
    agg_kernel<1><<<(NN + 3) / 4, 256>>>();                         // launch 7
    gemm_tc_kernel<<<ggrid, 256>>>(1, 1024 + 32, out);              // launch 8
    agg_kernel<2><<<(NN + 3) / 4, 256>>>();                         // launch 9
    gemm_tc_kernel<<<ggrid, 256>>>(2, 1280 + 32, out);              // launch 10
    agg_kernel<3><<<(NN + 3) / 4, 256>>>();                         // launch 11 (clears g_cnt)
    gemm_tc_kernel<<<ggrid, 256>>>(3, 1536 + 32, out);              // launch 12
}